// round 9
// baseline (speedup 1.0000x reference)
#include <cuda_runtime.h>
#include <math.h>

#define T_STEPS   32768
#define N_NEUR    1024
#define FILT_LEN  200
#define THREADS   256
#define PAD       64

#define LOG_DT_F      (-6.907755278982137f)
#define NOISE_SIGMA_F (0.2f)
#define FILT_DECAY_F  (0.05f)
#define INH_FACTOR_F  (0.8187307530779818f)
#define INH_INC_F     (3000.0f)

// scratch (no cudaMalloc allowed)
__device__ float          g_thr[T_STEPS];
__device__ unsigned short g_loc[T_STEPS];

// ---------------------------------------------------------------------------
// One block per time step t. Exact R3 producer (70us standalone): precise
// expf, tiny smem footprint (full L1D carveout), no fences/atomics.
// ---------------------------------------------------------------------------
__global__ void __launch_bounds__(THREADS)
row_kernel(const float* __restrict__ inputs,
           const float* __restrict__ noise_rand,
           const float* __restrict__ u_mult,
           const float* __restrict__ rand_val,
           float* __restrict__ out)
{
    const int t    = blockIdx.x;
    const int tid  = threadIdx.x;
    const int lane = tid & 31;
    const int wid  = tid >> 5;
    const unsigned FULL = 0xffffffffu;

    __shared__ float s_max[8];
    __shared__ float s_ns[8];
    __shared__ float s_wsum[8];
    __shared__ int   s_cnt[8];
    __shared__ float s_b[2];   // [0]=noise c, [1]=m' = rowmax + c

    const float4 x4 =
        reinterpret_cast<const float4*>(inputs)[(size_t)t * (N_NEUR / 4) + tid];

    // noise tap: noise[t] = sum_j nr[t-j] * exp(-j*0.05)
    float prod = 0.0f;
    if (tid < FILT_LEN) {
        int idx = t - tid;
        if (idx >= 0) {
            float nr   = noise_rand[idx] * NOISE_SIGMA_F;
            float filt = expf(-((float)tid) * FILT_DECAY_F);
            prod = nr * filt;
        }
    }

    // joint warp reduce: row max + noise sum
    float lm = fmaxf(fmaxf(x4.x, x4.y), fmaxf(x4.z, x4.w));
    #pragma unroll
    for (int o = 16; o; o >>= 1) {
        lm   = fmaxf(lm, __shfl_xor_sync(FULL, lm, o));
        prod += __shfl_xor_sync(FULL, prod, o);
    }
    if (lane == 0) { s_max[wid] = lm; s_ns[wid] = prod; }
    __syncthreads();
    if (tid == 0) {
        float m = s_max[0], c = s_ns[0];
        #pragma unroll
        for (int i = 1; i < 8; i++) { m = fmaxf(m, s_max[i]); c += s_ns[i]; }
        s_b[0] = c;
        s_b[1] = m + c;     // m' for inputs+noise (monotone rounding)
    }
    __syncthreads();
    const float c  = s_b[0];
    const float mp = s_b[1];

    const float e0 = expf((x4.x + c) - mp);
    const float e1 = expf((x4.y + c) - mp);
    const float e2 = expf((x4.z + c) - mp);
    const float e3 = expf((x4.w + c) - mp);
    const float p0 = e0;
    const float p1 = p0 + e1;
    const float p2 = p1 + e2;
    const float p3 = p2 + e3;

    float incl = p3;
    #pragma unroll
    for (int o = 1; o < 32; o <<= 1) {
        float n = __shfl_up_sync(FULL, incl, o);
        if (lane >= o) incl += n;
    }
    if (lane == 31) s_wsum[wid] = incl;
    __syncthreads();
    float warp_off = 0.0f, stot = 0.0f;
    {
        float acc = 0.0f;
        #pragma unroll
        for (int i = 0; i < 8; i++) {
            if (i == wid) warp_off = acc;
            acc += s_wsum[i];
        }
        stot = acc;
    }
    float excl = __shfl_up_sync(FULL, incl, 1);
    if (lane == 0) excl = 0.0f;
    const float base = warp_off + excl;

    const float us = u_mult[t] * stot;
    int cnt = (int)((base + p0) < us) + (int)((base + p1) < us)
            + (int)((base + p2) < us) + (int)((base + p3) < us);
    #pragma unroll
    for (int o = 16; o; o >>= 1) cnt += __shfl_xor_sync(FULL, cnt, o);
    if (lane == 0) s_cnt[wid] = cnt;
    __syncthreads();
    if (tid == 0) {
        int total = 0;
        #pragma unroll
        for (int i = 0; i < 8; i++) total += s_cnt[i];
        int loc = (total >= N_NEUR) ? 0 : total;
        g_loc[t] = (unsigned short)loc;
        const float logr = logf(rand_val[t]);
        g_thr[t] = ((logf(stot) + mp) + LOG_DT_F) - logr;
        out[(size_t)T_STEPS * N_NEUR + T_STEPS + t] = c;   // noise output
    }

    // zero-fill the out_spikes row (scan kernel scatters the rare 1.0s)
    reinterpret_cast<float4*>(out)[(size_t)t * (N_NEUR / 4) + tid] =
        make_float4(0.0f, 0.0f, 0.0f, 0.0f);
}

// ---------------------------------------------------------------------------
// Standalone scan. All thr/loc staged into 197KB dynamic smem first (8 warps,
// vectorized), then warp 0 runs the register-resident speculative decay scan:
//   window = 64 (2 positions/lane), per-lane F-power constants in registers,
//   full no-spike windows advance Wv *= F^64 (hoisted constant, no LDS on
//   the dependence chain), spikes resolved with 2 ballots + 1 shfl.
// ---------------------------------------------------------------------------
__global__ void __launch_bounds__(THREADS)
scan_kernel(float* __restrict__ out)
{
    extern __shared__ char smem[];
    float*          s_thr = reinterpret_cast<float*>(smem);
    unsigned short* s_loc =
        reinterpret_cast<unsigned short*>(smem + (T_STEPS + PAD) * sizeof(float));

    const int tid  = threadIdx.x;
    const int lane = tid & 31;
    const unsigned FULL = 0xffffffffu;
    const size_t IDX_INH = (size_t)T_STEPS * N_NEUR;

    // ---- stage thr (float4) + loc (uint2 = 4 shorts) into shared ----
    {
        const float4* src4 = reinterpret_cast<const float4*>(g_thr);
        float4*       dst4 = reinterpret_cast<float4*>(s_thr);
        for (int i = tid; i < T_STEPS / 4; i += THREADS) dst4[i] = src4[i];
        const uint2* srcl = reinterpret_cast<const uint2*>(g_loc);
        uint2*       dstl = reinterpret_cast<uint2*>(s_loc);
        for (int i = tid; i < T_STEPS / 4; i += THREADS) dstl[i] = srcl[i];
        for (int i = tid; i < PAD; i += THREADS) {
            s_thr[T_STEPS + i] = __int_as_float(0xff800000);  // -inf: never spikes
            s_loc[T_STEPS + i] = 0;
        }
    }
    __syncthreads();

    if (tid >= 32) return;     // warp 0 only

    // per-lane decay constants (double-accurate, single fp32 rounding)
    const int   l2  = lane << 1;
    const float C0  = (float)exp(-0.2 * (double)l2);        // F^(2l)
    const float C1  = (float)exp(-0.2 * (double)(l2 + 1));  // F^(2l+1)
    const float C2  = (float)exp(-0.2 * (double)(l2 + 2));  // F^(2l+2)
    const float C64 = (float)exp(-0.2 * 64.0);              // F^64 (window hop)

    // Scan state: Wv = w_p (inhibition value entering step p); w_{p+i} = Wv*F^i.
    float Wv = 0.0f;
    int   p  = 0;

    while (p < T_STEPS) {
        const float thr0 = s_thr[p + l2];
        const float thr1 = s_thr[p + l2 + 1];

        const float w0 = __fmul_rn(Wv, C0);     // w_{p+l2}
        const float w1 = __fmul_rn(Wv, C1);     // w_{p+l2+1}
        const float w2 = __fmul_rn(Wv, C2);     // w_{p+l2+2}

        const unsigned m0 = __ballot_sync(FULL, w0 < thr0);
        const unsigned m1 = __ballot_sync(FULL, w1 < thr1);

        if (m0 | m1) {
            const int j0 = m0 ? ((__ffs(m0) - 1) << 1)       : (1 << 30);
            const int j1 = m1 ? (((__ffs(m1) - 1) << 1) | 1) : (1 << 30);
            const int j  = min(j0, j1);          // first spike offset (p+j < T)

            // lane (j>>1) holds w_{j+1}: its w1 if the even slot fired first
            const float cand = ((m0 >> lane) & 1u) ? w1 : w2;
            const float wn   = __shfl_sync(FULL, cand, j >> 1);
            const float An   = __fadd_rn(wn, INH_INC_F);   // serial: w_j*F + 3000

            if (l2 < j)           out[IDX_INH + (p + l2)]     = w1;
            else if (l2 == j)     out[IDX_INH + (p + l2)]     = An;
            if (l2 + 1 < j)       out[IDX_INH + (p + l2 + 1)] = w2;
            else if (l2 + 1 == j) out[IDX_INH + (p + l2 + 1)] = An;

            if (lane == (j >> 1)) {
                const int ts = p + j;
                out[(size_t)ts * N_NEUR + (int)s_loc[ts]] = 1.0f;
            }
            Wv = An; p += j + 1;
        } else {
            const int rem = T_STEPS - p;
            if (l2 < rem)     out[IDX_INH + (p + l2)]     = w1;
            if (l2 + 1 < rem) out[IDX_INH + (p + l2 + 1)] = w2;
            Wv = __fmul_rn(Wv, C64);             // constant hop, no LDS
            p += PAD;
        }
    }
}

extern "C" void kernel_launch(void* const* d_in, const int* in_sizes, int n_in,
                              void* d_out, int out_size)
{
    const float* inputs     = (const float*)d_in[0];
    const float* noise_rand = (const float*)d_in[1];
    const float* u_mult     = (const float*)d_in[2];
    const float* rand_val   = (const float*)d_in[3];
    float* out = (float*)d_out;

    const size_t smem_bytes =
        (size_t)(T_STEPS + PAD) * sizeof(float) +
        (size_t)(T_STEPS + PAD) * sizeof(unsigned short);

    static int configured = 0;
    if (!configured) {
        cudaFuncSetAttribute(scan_kernel,
                             cudaFuncAttributeMaxDynamicSharedMemorySize,
                             (int)smem_bytes);
        configured = 1;
    }

    row_kernel<<<T_STEPS, THREADS>>>(inputs, noise_rand, u_mult, rand_val, out);
    scan_kernel<<<1, THREADS, smem_bytes>>>(out);
}

// round 10
// speedup vs baseline: 1.5823x; 1.5823x over previous
#include <cuda_runtime.h>
#include <math.h>

#define T_STEPS   32768
#define N_NEUR    1024
#define FILT_LEN  200
#define THREADS   256
#define CHUNK     1024
#define NCH       (T_STEPS / CHUNK)
#define PAD       64
#define NBUF      3
#define FTAB      1024
#define MAXSPK    4096

#define LOG_DT_F      (-6.907755278982137f)
#define NOISE_SIGMA_F (0.2f)
#define INH_INC_F     (3000.0f)

// scratch (no cudaMalloc allowed)
__device__ float          g_thr[T_STEPS];
__device__ unsigned short g_loc[T_STEPS];
__device__ int            g_cnt[NCH * 32];     // one counter per 128B line
__device__ float          g_filt[FILT_LEN];    // FIR taps
__device__ int            g_spk_t[MAXSPK];     // spike times
__device__ float          g_spk_a[MAXSPK];     // post-spike amplitudes

__global__ void init_kernel() {
    const int i = threadIdx.x;
    if (i < NCH * 32) g_cnt[i] = 0;
    if (i < FILT_LEN) g_filt[i] = expf(-((float)i) * 0.05f);
}

// ---------------------------------------------------------------------------
// Fused kernel. Block 0 = persistent scanner; blocks 1..T_STEPS = producers.
// Scanner phase 1 finds spikes only (branch-free warp-0 loop, no stores on the
// chain); phase 2 (all 256 threads) reconstructs inhibition + scatters spikes.
// Chunk pipeline is pad-ahead: scanning chunk ch requires ch+1 staged; staging
// chunk cn also fills chunk cn-1's 64-entry pad, so windows cross chunk
// boundaries on real thr data with zero boundary logic.
// ---------------------------------------------------------------------------
__global__ void __launch_bounds__(THREADS)
fused_kernel(const float* __restrict__ inputs,
             const float* __restrict__ noise_rand,
             const float* __restrict__ u_mult,
             const float* __restrict__ rand_val,
             float* __restrict__ out)
{
    const int tid  = threadIdx.x;
    const int lane = tid & 31;
    const unsigned FULL = 0xffffffffu;
    const size_t IDX_INH = (size_t)T_STEPS * N_NEUR;

    __shared__ float s_thr[NBUF][CHUNK + PAD];
    __shared__ float s_fp[FTAB + 1];
    __shared__ int   s_nspk;
    __shared__ float s_max[8];
    __shared__ float s_ns[8];
    __shared__ float s_wsum[8];
    __shared__ int   s_cnt[8];
    __shared__ float s_b[2];

    if (blockIdx.x != 0) {
        // =================== PRODUCER: row t = blockIdx.x - 1 ===============
        const int t   = blockIdx.x - 1;
        const int wid = tid >> 5;

        const float4 x4 =
            reinterpret_cast<const float4*>(inputs)[(size_t)t * (N_NEUR / 4) + tid];

        // noise tap (table'd FIR — validated in R7)
        float prod = 0.0f;
        if (tid < FILT_LEN) {
            int idx = t - tid;
            if (idx >= 0) prod = (noise_rand[idx] * NOISE_SIGMA_F) * g_filt[tid];
        }

        float lm = fmaxf(fmaxf(x4.x, x4.y), fmaxf(x4.z, x4.w));
        #pragma unroll
        for (int o = 16; o; o >>= 1) {
            lm   = fmaxf(lm, __shfl_xor_sync(FULL, lm, o));
            prod += __shfl_xor_sync(FULL, prod, o);
        }
        if (lane == 0) { s_max[wid] = lm; s_ns[wid] = prod; }
        __syncthreads();
        if (tid == 0) {
            float m = s_max[0], c = s_ns[0];
            #pragma unroll
            for (int i = 1; i < 8; i++) { m = fmaxf(m, s_max[i]); c += s_ns[i]; }
            s_b[0] = c;
            s_b[1] = m + c;
        }
        __syncthreads();
        const float c  = s_b[0];
        const float mp = s_b[1];

        // fast exp (validated in R7: identical rel_err, no decision flips)
        const float e0 = __expf((x4.x + c) - mp);
        const float e1 = __expf((x4.y + c) - mp);
        const float e2 = __expf((x4.z + c) - mp);
        const float e3 = __expf((x4.w + c) - mp);
        const float p0 = e0;
        const float p1 = p0 + e1;
        const float p2 = p1 + e2;
        const float p3 = p2 + e3;

        float incl = p3;
        #pragma unroll
        for (int o = 1; o < 32; o <<= 1) {
            float n = __shfl_up_sync(FULL, incl, o);
            if (lane >= o) incl += n;
        }
        if (lane == 31) s_wsum[wid] = incl;
        __syncthreads();
        float warp_off = 0.0f, stot = 0.0f;
        {
            float acc = 0.0f;
            #pragma unroll
            for (int i = 0; i < 8; i++) {
                if (i == wid) warp_off = acc;
                acc += s_wsum[i];
            }
            stot = acc;
        }
        float excl = __shfl_up_sync(FULL, incl, 1);
        if (lane == 0) excl = 0.0f;
        const float base = warp_off + excl;

        const float us = u_mult[t] * stot;
        int cnt = (int)((base + p0) < us) + (int)((base + p1) < us)
                + (int)((base + p2) < us) + (int)((base + p3) < us);
        #pragma unroll
        for (int o = 16; o; o >>= 1) cnt += __shfl_xor_sync(FULL, cnt, o);
        if (lane == 0) s_cnt[wid] = cnt;
        __syncthreads();
        if (tid == 0) {
            int total = 0;
            #pragma unroll
            for (int i = 0; i < 8; i++) total += s_cnt[i];
            int loc = (total >= N_NEUR) ? 0 : total;
            g_loc[t] = (unsigned short)loc;
            const float logr = logf(rand_val[t]);
            g_thr[t] = ((logf(stot) + mp) + LOG_DT_F) - logr;
            out[IDX_INH + T_STEPS + t] = c;    // noise output
        }

        // zero-fill the out_spikes row (scanner scatters the rare 1.0s)
        reinterpret_cast<float4*>(out)[(size_t)t * (N_NEUR / 4) + tid] =
            make_float4(0.0f, 0.0f, 0.0f, 0.0f);

        // release: one fence + one atomic per block
        __syncthreads();
        if (tid == 0) {
            __threadfence();
            atomicAdd(&g_cnt[(t >> 10) << 5], 1);
        }
        return;
    }

    // ======================= SCANNER (block 0) ==============================
    // F^i table, double-accurate, single fp32 rounding (0 beyond underflow)
    for (int i = tid; i <= FTAB; i += THREADS)
        s_fp[i] = (float)exp(-0.2 * (double)i);
    __syncthreads();

    // ---- prologue: stage chunk 0, then chunk 1 (+ pads of chunk 0) ----
    if (tid == 0) {
        while (*((volatile int*)&g_cnt[0]) < CHUNK) __nanosleep(256);
        __threadfence();
    }
    __syncthreads();
    for (int i = tid; i < CHUNK; i += THREADS) s_thr[0][i] = g_thr[i];
    if (tid == 0) {
        while (*((volatile int*)&g_cnt[1 << 5]) < CHUNK) __nanosleep(256);
        __threadfence();
    }
    __syncthreads();
    for (int i = tid; i < CHUNK; i += THREADS) s_thr[1][i] = g_thr[CHUNK + i];
    for (int i = tid; i < PAD;   i += THREADS) s_thr[0][CHUNK + i] = g_thr[CHUNK + i];
    __syncthreads();

    // per-lane decay constants (registers)
    const int   l2  = lane << 1;
    const float C0  = s_fp[l2];
    const float C1  = s_fp[l2 + 1];
    const float C2  = s_fp[l2 + 2];
    const float C64 = s_fp[PAD];

    // phase-1 state (warp 0 registers; uniform across lanes)
    float Wv  = 0.0f;
    int   p   = 0;
    int   nsp = 0;

    for (int ch = 0; ch < NCH; ++ch) {
        if (tid < 32) {
            // ---- warp 0: spike-finding scan of chunk ch (branch-free) ----
            const float* tb   = s_thr[ch % NBUF];
            const int    cb   = ch * CHUNK;
            const int    cend = cb + CHUNK;

            while (p < cend) {
                const int   i0   = (p - cb) + l2;
                const float thr0 = tb[i0];
                const float thr1 = tb[i0 + 1];

                const float w0 = __fmul_rn(Wv, C0);
                const float w1 = __fmul_rn(Wv, C1);
                const float w2 = __fmul_rn(Wv, C2);

                const unsigned m0 = __ballot_sync(FULL, w0 < thr0);
                const unsigned m1 = __ballot_sync(FULL, w1 < thr1);
                const bool  spike = (m0 | m1) != 0u;

                const int j0 = m0 ? ((__ffs(m0) - 1) << 1)       : 0x7fffffff;
                const int j1 = m1 ? (((__ffs(m1) - 1) << 1) | 1) : 0x7fffffff;
                const int j  = min(j0, j1);

                const float cand = ((m0 >> lane) & 1u) ? w1 : w2;
                const float wn   = __shfl_sync(FULL, cand, (j >> 1) & 31);
                const float An   = __fadd_rn(wn, INH_INC_F);

                if (spike && lane == 0 && nsp < MAXSPK) {
                    g_spk_t[nsp] = p + j;
                    g_spk_a[nsp] = An;
                }
                nsp += (int)spike;
                Wv = spike ? An : __fmul_rn(Wv, C64);
                p += spike ? (j + 1) : PAD;
            }
        } else {
            // ---- warps 1..7: stage chunk ch+2 (+ pads of chunk ch+1) ----
            const int cn = ch + 2;
            if (cn < NCH) {
                if (lane == 0) {
                    while (*((volatile int*)&g_cnt[cn << 5]) < CHUNK)
                        __nanosleep(256);
                    __threadfence();
                }
                __syncwarp();
                float*       dm  = s_thr[cn % NBUF];
                float*       dp  = s_thr[(cn + NBUF - 1) % NBUF];
                const int    off = cn * CHUNK;
                for (int i = tid - 32; i < CHUNK; i += THREADS - 32)
                    dm[i] = g_thr[off + i];
                for (int i = tid - 32; i < PAD; i += THREADS - 32)
                    dp[CHUNK + i] = g_thr[off + i];
            } else if (cn == NCH) {
                // -inf pads for the last chunk: never spikes past T
                float* dp = s_thr[(NCH - 1) % NBUF];
                for (int i = tid - 32; i < PAD; i += THREADS - 32)
                    dp[CHUNK + i] = __int_as_float(0xff800000);
            }
        }
        __syncthreads();
    }

    if (tid == 0) s_nspk = min(nsp, MAXSPK);
    __syncthreads();

    // ======================= PHASE 2: reconstruction ========================
    // inh[t] = An_s * F^(t - ts_s) for the last spike s at/before t (0 before
    // the first spike). One-hot spike scatter at each spike time.
    {
        const int ns = s_nspk;
        const int t0 = tid * (T_STEPS / THREADS);
        const int t1 = t0 + (T_STEPS / THREADS);

        // binary search: s = last spike with ts < t0
        int lo = 0, hi = ns;
        while (lo < hi) {
            const int mid = (lo + hi) >> 1;
            if (g_spk_t[mid] < t0) lo = mid + 1; else hi = mid;
        }
        int   s    = lo - 1;
        float A    = (s >= 0) ? g_spk_a[s] : 0.0f;
        int   base = (s >= 0) ? g_spk_t[s] : t0;
        int   next = (s + 1 < ns) ? g_spk_t[s + 1] : 0x7fffffff;

        for (int t = t0; t < t1; ++t) {
            float val;
            if (t == next) {
                ++s;
                A    = g_spk_a[s];
                base = t;
                next = (s + 1 < ns) ? g_spk_t[s + 1] : 0x7fffffff;
                out[(size_t)t * N_NEUR + (int)g_loc[t]] = 1.0f;
                val = A;
            } else {
                val = __fmul_rn(A, s_fp[min(t - base, FTAB)]);
            }
            out[IDX_INH + t] = val;
        }
    }
}

extern "C" void kernel_launch(void* const* d_in, const int* in_sizes, int n_in,
                              void* d_out, int out_size)
{
    const float* inputs     = (const float*)d_in[0];
    const float* noise_rand = (const float*)d_in[1];
    const float* u_mult     = (const float*)d_in[2];
    const float* rand_val   = (const float*)d_in[3];
    float* out = (float*)d_out;

    init_kernel<<<1, 1024>>>();
    fused_kernel<<<T_STEPS + 1, THREADS>>>(inputs, noise_rand, u_mult, rand_val, out);
}